// round 2
// baseline (speedup 1.0000x reference)
#include <cuda_runtime.h>
#include <cuda_bf16.h>

#define B_   32
#define C_   768
#define CR_  192
#define HW_  1024          // 32*32, contiguous per (b,c)
#define BC_  (B_ * C_)     // 24576
#define N4_  (BC_ * HW_ / 4)  // total float4 = 6,291,456

// Scratch (device globals — no allocation allowed in kernel_launch)
__device__ float d_s[BC_];   // pooled means [B, C]
__device__ float d_g[BC_];   // gates       [B, C]

// ---------------------------------------------------------------------------
// Kernel 1: global average pool. One warp per (b,c) channel.
// Channel data is contiguous: 1024 floats = 256 float4. 8 float4 per lane.
// ---------------------------------------------------------------------------
__global__ __launch_bounds__(256) void pool_kernel(const float* __restrict__ x) {
    int gwarp = (blockIdx.x * 256 + threadIdx.x) >> 5;   // channel index
    int lane  = threadIdx.x & 31;
    if (gwarp >= BC_) return;

    const float4* p = reinterpret_cast<const float4*>(x) + (size_t)gwarp * 256;
    float sum = 0.0f;
#pragma unroll
    for (int i = 0; i < 8; i++) {
        float4 v = p[lane + i * 32];
        sum += (v.x + v.y) + (v.z + v.w);
    }
#pragma unroll
    for (int o = 16; o; o >>= 1) sum += __shfl_xor_sync(0xffffffffu, sum, o);
    if (lane == 0) d_s[gwarp] = sum * (1.0f / 1024.0f);
}

// ---------------------------------------------------------------------------
// Kernel 2: tiny MLP. One CTA per batch row (32 CTAs, 256 thr).
//   h = swish(s @ w1^T + b1)   [192]
//   g = sigmoid(h @ w2^T + b2) [768]
// Warp-per-output, lanes stride over k (coalesced weight-row reads).
// ---------------------------------------------------------------------------
__global__ __launch_bounds__(256) void mlp_kernel(const float* __restrict__ w1,
                                                  const float* __restrict__ b1,
                                                  const float* __restrict__ w2,
                                                  const float* __restrict__ b2) {
    __shared__ float s_sm[C_];
    __shared__ float h_sm[CR_];

    int b    = blockIdx.x;
    int tid  = threadIdx.x;
    int warp = tid >> 5;
    int lane = tid & 31;

    for (int i = tid; i < C_; i += 256) s_sm[i] = d_s[b * C_ + i];
    __syncthreads();

    // Phase 1: 192 outputs, 8 warps -> 24 outputs per warp.
    for (int j = warp; j < CR_; j += 8) {
        const float* wr = w1 + (size_t)j * C_;
        float acc = 0.0f;
#pragma unroll 4
        for (int k = lane; k < C_; k += 32) acc += s_sm[k] * wr[k];
#pragma unroll
        for (int o = 16; o; o >>= 1) acc += __shfl_xor_sync(0xffffffffu, acc, o);
        if (lane == 0) {
            float h = acc + b1[j];
            h_sm[j] = h / (1.0f + expf(-h));   // swish
        }
    }
    __syncthreads();

    // Phase 2: 768 outputs, 8 warps -> 96 per warp.
    for (int c = warp; c < C_; c += 8) {
        const float* wr = w2 + (size_t)c * CR_;
        float acc = 0.0f;
#pragma unroll
        for (int k = lane; k < CR_; k += 32) acc += h_sm[k] * wr[k];
#pragma unroll
        for (int o = 16; o; o >>= 1) acc += __shfl_xor_sync(0xffffffffu, acc, o);
        if (lane == 0)
            d_g[b * C_ + c] = 1.0f / (1.0f + expf(-(acc + b2[c])));
    }
}

// ---------------------------------------------------------------------------
// Kernel 3: out = x * g broadcast. One float4 per thread.
// float4 index i -> channel i >> 8 (1024 floats = 256 float4 per channel).
// ---------------------------------------------------------------------------
__global__ __launch_bounds__(256) void scale_kernel(const float* __restrict__ x,
                                                    float* __restrict__ out) {
    int i = blockIdx.x * 256 + threadIdx.x;   // float4 index, grid sized exactly
    float g = d_g[i >> 8];
    float4 v = reinterpret_cast<const float4*>(x)[i];
    v.x *= g; v.y *= g; v.z *= g; v.w *= g;
    reinterpret_cast<float4*>(out)[i] = v;
}

// ---------------------------------------------------------------------------
extern "C" void kernel_launch(void* const* d_in, const int* in_sizes, int n_in,
                              void* d_out, int out_size) {
    const float* x  = (const float*)d_in[0];
    const float* w1 = (const float*)d_in[1];
    const float* b1 = (const float*)d_in[2];
    const float* w2 = (const float*)d_in[3];
    const float* b2 = (const float*)d_in[4];
    float* out = (float*)d_out;

    pool_kernel<<<BC_ / 8, 256>>>(x);                 // 3072 CTAs, warp/channel
    mlp_kernel<<<B_, 256>>>(w1, b1, w2, b2);          // 32 CTAs
    scale_kernel<<<N4_ / 256, 256>>>(x, out);         // 24576 CTAs
}

// round 3
// speedup vs baseline: 3.0909x; 3.0909x over previous
#include <cuda_runtime.h>
#include <cuda_bf16.h>

#define B_   32
#define C_   768
#define CR_  192
#define HW_  1024          // 32*32, contiguous per (b,c)
#define BC_  (B_ * C_)     // 24576
#define BCR_ (B_ * CR_)    // 6144
#define N4_  (BC_ * HW_ / 4)  // total float4 = 6,291,456

// Scratch (device globals — no allocation allowed in kernel_launch)
__device__ float d_s[BC_];    // pooled means [B, C]
__device__ float d_h[BCR_];   // hidden (swish) [B, Cr]
__device__ float d_g[BC_];    // gates [B, C]

// ---------------------------------------------------------------------------
// Kernel 1: global average pool. One warp per (b,c) channel.
// Channel data contiguous: 1024 floats = 256 float4, 8 per lane.
// ---------------------------------------------------------------------------
__global__ __launch_bounds__(256) void pool_kernel(const float* __restrict__ x) {
    int ch   = (blockIdx.x * 256 + threadIdx.x) >> 5;
    int lane = threadIdx.x & 31;

    const float4* p = reinterpret_cast<const float4*>(x) + (size_t)ch * 256;
    float sum = 0.0f;
#pragma unroll
    for (int i = 0; i < 8; i++) {
        float4 v = p[lane + i * 32];
        sum += (v.x + v.y) + (v.z + v.w);
    }
#pragma unroll
    for (int o = 16; o; o >>= 1) sum += __shfl_xor_sync(0xffffffffu, sum, o);
    if (lane == 0) d_s[ch] = sum * (1.0f / 1024.0f);
}

// ---------------------------------------------------------------------------
// Kernel 2a: h = swish(s @ w1^T + b1). Warp per (b, j) dot of length 768.
// 6144 warps -> 768 CTAs x 8 warps: one wave, loads fully overlapped chipwide.
// ---------------------------------------------------------------------------
__global__ __launch_bounds__(256) void mlp1_kernel(const float* __restrict__ w1,
                                                   const float* __restrict__ b1) {
    int gw   = (blockIdx.x * 256 + threadIdx.x) >> 5;   // 0..6143
    int lane = threadIdx.x & 31;
    int j = gw % CR_;          // hidden index (consecutive warps in CTA share b)
    int b = gw / CR_;          // batch

    const float* wr = w1 + (size_t)j * C_;
    const float* sr = d_s + b * C_;
    float acc = 0.0f;
#pragma unroll
    for (int t = 0; t < C_ / 32; t++) {                 // 24 independent loads
        int k = lane + t * 32;
        acc += sr[k] * wr[k];
    }
#pragma unroll
    for (int o = 16; o; o >>= 1) acc += __shfl_xor_sync(0xffffffffu, acc, o);
    if (lane == 0) {
        float h = acc + b1[j];
        d_h[b * CR_ + j] = h / (1.0f + __expf(-h));     // swish
    }
}

// ---------------------------------------------------------------------------
// Kernel 2b: g = sigmoid(h @ w2^T + b2). Warp per (b, c) dot of length 192.
// 24576 warps -> 3072 CTAs x 8 warps.
// ---------------------------------------------------------------------------
__global__ __launch_bounds__(256) void mlp2_kernel(const float* __restrict__ w2,
                                                   const float* __restrict__ b2) {
    int gw   = (blockIdx.x * 256 + threadIdx.x) >> 5;   // 0..24575
    int lane = threadIdx.x & 31;
    int c = gw % C_;
    int b = gw / C_;

    const float* wr = w2 + (size_t)c * CR_;
    const float* hr = d_h + b * CR_;
    float acc = 0.0f;
#pragma unroll
    for (int t = 0; t < CR_ / 32; t++) {                // 6 independent loads
        int k = lane + t * 32;
        acc += hr[k] * wr[k];
    }
#pragma unroll
    for (int o = 16; o; o >>= 1) acc += __shfl_xor_sync(0xffffffffu, acc, o);
    if (lane == 0)
        d_g[b * C_ + c] = 1.0f / (1.0f + __expf(-(acc + b2[c])));
}

// ---------------------------------------------------------------------------
// Kernel 3: out = x * g broadcast. One float4 per thread.
// float4 index i -> channel i >> 8.
// ---------------------------------------------------------------------------
__global__ __launch_bounds__(256) void scale_kernel(const float* __restrict__ x,
                                                    float* __restrict__ out) {
    int i = blockIdx.x * 256 + threadIdx.x;
    float g = d_g[i >> 8];
    float4 v = reinterpret_cast<const float4*>(x)[i];
    v.x *= g; v.y *= g; v.z *= g; v.w *= g;
    reinterpret_cast<float4*>(out)[i] = v;
}

// ---------------------------------------------------------------------------
extern "C" void kernel_launch(void* const* d_in, const int* in_sizes, int n_in,
                              void* d_out, int out_size) {
    const float* x  = (const float*)d_in[0];
    const float* w1 = (const float*)d_in[1];
    const float* b1 = (const float*)d_in[2];
    const float* w2 = (const float*)d_in[3];
    const float* b2 = (const float*)d_in[4];
    float* out = (float*)d_out;

    pool_kernel<<<BC_ / 8, 256>>>(x);            // 3072 CTAs
    mlp1_kernel<<<BCR_ / 8, 256>>>(w1, b1);      // 768 CTAs, warp/dot
    mlp2_kernel<<<BC_ / 8, 256>>>(w2, b2);       // 3072 CTAs, warp/dot
    scale_kernel<<<N4_ / 256, 256>>>(x, out);    // 24576 CTAs
}

// round 4
// speedup vs baseline: 3.3197x; 1.0741x over previous
#include <cuda_runtime.h>
#include <cuda_bf16.h>

#define B_   32
#define C_   768
#define CR_  192
#define HW_  1024          // 32*32, contiguous per (b,c)
#define BC_  (B_ * C_)     // 24576
#define BCR_ (B_ * CR_)    // 6144

// Scratch (device globals — no allocation allowed in kernel_launch)
__device__ float d_s[BC_];    // pooled means [B, C]
__device__ float d_h[BCR_];   // hidden (swish) [B, Cr]

// ---------------------------------------------------------------------------
// Kernel 1: global average pool. One warp per (b,c) channel.
// Channel data contiguous: 1024 floats = 256 float4, 8 per lane.
// Default-cached loads deliberately leave x resident in L2 for the scale pass.
// ---------------------------------------------------------------------------
__global__ __launch_bounds__(256) void pool_kernel(const float* __restrict__ x) {
    int ch   = (blockIdx.x * 256 + threadIdx.x) >> 5;
    int lane = threadIdx.x & 31;

    const float4* p = reinterpret_cast<const float4*>(x) + (size_t)ch * 256;
    float sum = 0.0f;
#pragma unroll
    for (int i = 0; i < 8; i++) {
        float4 v = p[lane + i * 32];
        sum += (v.x + v.y) + (v.z + v.w);
    }
#pragma unroll
    for (int o = 16; o; o >>= 1) sum += __shfl_xor_sync(0xffffffffu, sum, o);
    if (lane == 0) d_s[ch] = sum * (1.0f / 1024.0f);
}

// ---------------------------------------------------------------------------
// Kernel 2: h = swish(s @ w1^T + b1). Warp per (b, j) dot of length 768.
// 6144 warps -> 768 CTAs x 8 warps: one wave, loads overlapped chipwide.
// ---------------------------------------------------------------------------
__global__ __launch_bounds__(256) void mlp1_kernel(const float* __restrict__ w1,
                                                   const float* __restrict__ b1) {
    int gw   = (blockIdx.x * 256 + threadIdx.x) >> 5;   // 0..6143
    int lane = threadIdx.x & 31;
    int j = gw % CR_;
    int b = gw / CR_;

    const float* wr = w1 + (size_t)j * C_;
    const float* sr = d_s + b * C_;
    float acc = 0.0f;
#pragma unroll
    for (int t = 0; t < C_ / 32; t++) {                 // 24 independent loads
        int k = lane + t * 32;
        acc += sr[k] * wr[k];
    }
#pragma unroll
    for (int o = 16; o; o >>= 1) acc += __shfl_xor_sync(0xffffffffu, acc, o);
    if (lane == 0) {
        float h = acc + b1[j];
        d_h[b * CR_ + j] = h / (1.0f + __expf(-h));     // swish
    }
}

// ---------------------------------------------------------------------------
// Kernel 3: fused gate + scale. One CTA per (b,c) channel (256 thr, 1 float4
// each). Warp 0 computes g = sigmoid(<h[b,:], w2[c,:]> + b2[c]) while all
// threads load their x float4; smem broadcast; multiply; evict-first store so
// output traffic does not evict x's L2 footprint ahead of the read stream.
// ---------------------------------------------------------------------------
__global__ __launch_bounds__(256) void scale_kernel(const float* __restrict__ x,
                                                    const float* __restrict__ w2,
                                                    const float* __restrict__ b2,
                                                    float* __restrict__ out) {
    __shared__ float g_sm;
    int ch   = blockIdx.x;            // (b*C_ + c)
    int tid  = threadIdx.x;

    // Start the x load immediately (independent of the gate).
    const float4* xp = reinterpret_cast<const float4*>(x) + (size_t)ch * 256 + tid;
    float4 v = __ldcs(xp);            // evict-first: last use of this line

    if (tid < 32) {                   // warp 0: 192-length dot
        int c = ch & (C_ - 1);        // C_=768 not pow2 -> compute properly
        c = ch % C_;
        int b = ch / C_;
        const float* wr = w2 + (size_t)c * CR_;
        const float* hr = d_h + b * CR_;
        float acc = 0.0f;
#pragma unroll
        for (int t = 0; t < CR_ / 32; t++) {
            int k = tid + t * 32;
            acc += hr[k] * wr[k];
        }
#pragma unroll
        for (int o = 16; o; o >>= 1) acc += __shfl_xor_sync(0xffffffffu, acc, o);
        if (tid == 0)
            g_sm = 1.0f / (1.0f + __expf(-(acc + b2[c])));
    }
    __syncthreads();

    float g = g_sm;
    v.x *= g; v.y *= g; v.z *= g; v.w *= g;
    __stcs(reinterpret_cast<float4*>(out) + (size_t)ch * 256 + tid, v);
}

// ---------------------------------------------------------------------------
extern "C" void kernel_launch(void* const* d_in, const int* in_sizes, int n_in,
                              void* d_out, int out_size) {
    const float* x  = (const float*)d_in[0];
    const float* w1 = (const float*)d_in[1];
    const float* b1 = (const float*)d_in[2];
    const float* w2 = (const float*)d_in[3];
    const float* b2 = (const float*)d_in[4];
    float* out = (float*)d_out;

    pool_kernel<<<BC_ / 8, 256>>>(x);            // 3072 CTAs
    mlp1_kernel<<<BCR_ / 8, 256>>>(w1, b1);      // 768 CTAs, warp/dot
    scale_kernel<<<BC_, 256>>>(x, w2, b2, out);  // 24576 CTAs, CTA/channel
}

// round 6
// speedup vs baseline: 3.4118x; 1.0277x over previous
#include <cuda_runtime.h>
#include <cuda_bf16.h>

#define B_   32
#define C_   768
#define CR_  192
#define HW_  1024          // 32*32, contiguous per (b,c)
#define BC_  (B_ * C_)     // 24576
#define BCR_ (B_ * CR_)    // 6144

// Scratch (device globals — no allocation allowed in kernel_launch)
__device__ float d_s[BC_];    // pooled means [B, C]
__device__ float d_h[BCR_];   // hidden (swish) [B, Cr]

// 32-byte L2-persist load (sm_103a: evict_last requires .v8.b32 width).
struct F8 { float a0,a1,a2,a3,a4,a5,a6,a7; };
__device__ __forceinline__ F8 ld_evict_last_32B(const void* p) {
    F8 v;
    asm volatile(
        "ld.global.L2::evict_last.v8.b32 {%0,%1,%2,%3,%4,%5,%6,%7}, [%8];"
        : "=f"(v.a0), "=f"(v.a1), "=f"(v.a2), "=f"(v.a3),
          "=f"(v.a4), "=f"(v.a5), "=f"(v.a6), "=f"(v.a7)
        : "l"(p));
    return v;
}

// ---------------------------------------------------------------------------
// Kernel 1: global average pool. One warp per (b,c) channel.
// 1024 floats = 128 x 32B chunks; 4 chunks per lane, evict_last so x stays
// resident in L2 for the scale pass.
// ---------------------------------------------------------------------------
__global__ __launch_bounds__(256) void pool_kernel(const float* __restrict__ x) {
    int ch   = (blockIdx.x * 256 + threadIdx.x) >> 5;
    int lane = threadIdx.x & 31;

    const char* base = reinterpret_cast<const char*>(x) + (size_t)ch * 4096;
    float sum = 0.0f;
#pragma unroll
    for (int i = 0; i < 4; i++) {
        F8 v = ld_evict_last_32B(base + (lane + i * 32) * 32);
        sum += ((v.a0 + v.a1) + (v.a2 + v.a3)) + ((v.a4 + v.a5) + (v.a6 + v.a7));
    }
#pragma unroll
    for (int o = 16; o; o >>= 1) sum += __shfl_xor_sync(0xffffffffu, sum, o);
    if (lane == 0) d_s[ch] = sum * (1.0f / 1024.0f);
}

// ---------------------------------------------------------------------------
// Kernel 2: h = swish(s @ w1^T + b1). Warp per (b, j) dot of length 768.
// ---------------------------------------------------------------------------
__global__ __launch_bounds__(256) void mlp1_kernel(const float* __restrict__ w1,
                                                   const float* __restrict__ b1) {
    int gw   = (blockIdx.x * 256 + threadIdx.x) >> 5;   // 0..6143
    int lane = threadIdx.x & 31;
    int j = gw % CR_;
    int b = gw / CR_;

    const float* wr = w1 + (size_t)j * C_;
    const float* sr = d_s + b * C_;
    float acc = 0.0f;
#pragma unroll
    for (int t = 0; t < C_ / 32; t++) {                 // 24 independent loads
        int k = lane + t * 32;
        acc += sr[k] * wr[k];
    }
#pragma unroll
    for (int o = 16; o; o >>= 1) acc += __shfl_xor_sync(0xffffffffu, acc, o);
    if (lane == 0) {
        float h = acc + b1[j];
        d_h[b * CR_ + j] = h / (1.0f + __expf(-h));     // swish
    }
}

// ---------------------------------------------------------------------------
// Kernel 3: fused gate + scale. One CTA per (b,c) channel, REVERSED order so
// the scale pass consumes the MRU tail of pool's L2 stream first. Warp 0
// computes g = sigmoid(<h[b,:], w2[c,:]> + b2[c]) concurrently with the x
// loads; evict-first reads (last use) and evict-first stores (no pollution).
// ---------------------------------------------------------------------------
__global__ __launch_bounds__(256) void scale_kernel(const float* __restrict__ x,
                                                    const float* __restrict__ w2,
                                                    const float* __restrict__ b2,
                                                    float* __restrict__ out) {
    __shared__ float g_sm;
    int ch  = (BC_ - 1) - blockIdx.x;   // reverse traversal
    int tid = threadIdx.x;

    const float4* xp = reinterpret_cast<const float4*>(x) + (size_t)ch * 256 + tid;
    float4 v = __ldcs(xp);              // independent of the gate; starts first

    if (tid < 32) {                     // warp 0: 192-length dot
        int c = ch % C_;
        int b = ch / C_;
        const float* wr = w2 + (size_t)c * CR_;
        const float* hr = d_h + b * CR_;
        float acc = 0.0f;
#pragma unroll
        for (int t = 0; t < CR_ / 32; t++) {
            int k = tid + t * 32;
            acc += hr[k] * wr[k];
        }
#pragma unroll
        for (int o = 16; o; o >>= 1) acc += __shfl_xor_sync(0xffffffffu, acc, o);
        if (tid == 0)
            g_sm = 1.0f / (1.0f + __expf(-(acc + b2[c])));
    }
    __syncthreads();

    float g = g_sm;
    v.x *= g; v.y *= g; v.z *= g; v.w *= g;
    __stcs(reinterpret_cast<float4*>(out) + (size_t)ch * 256 + tid, v);
}

// ---------------------------------------------------------------------------
extern "C" void kernel_launch(void* const* d_in, const int* in_sizes, int n_in,
                              void* d_out, int out_size) {
    const float* x  = (const float*)d_in[0];
    const float* w1 = (const float*)d_in[1];
    const float* b1 = (const float*)d_in[2];
    const float* w2 = (const float*)d_in[3];
    const float* b2 = (const float*)d_in[4];
    float* out = (float*)d_out;

    pool_kernel<<<BC_ / 8, 256>>>(x);            // 3072 CTAs
    mlp1_kernel<<<BCR_ / 8, 256>>>(w1, b1);      // 768 CTAs, warp/dot
    scale_kernel<<<BC_, 256>>>(x, w2, b2, out);  // 24576 CTAs, CTA/channel
}